// round 6
// baseline (speedup 1.0000x reference)
#include <cuda_runtime.h>
#include <cuda_bf16.h>
#include <math.h>
#include <stdint.h>

// ---------------- problem constants ----------------
#define BB    32
#define LL    1024
#define CIN   32
#define DM    512
#define NMARK 4
#define GG    4
#define DG    128
#define DIN   256
#define NST   16
#define DTR   8
#define PATCH 16
#define PRED  96
#define NTOK  (BB*PRED)      // 3072 tokens actually needed
#define NEXT  98             // extended token set per batch: l=0 and l=927..1023
#define KE    112            // embed K padded to multiple of 16 (100 -> 112)
#define LN1E4 9.210340371976184f

// ---------------- tf32 split helpers ----------------
__device__ __forceinline__ uint32_t f2tf32(float v) {
    uint32_t r; asm("cvt.rna.tf32.f32 %0, %1;" : "=r"(r) : "f"(v)); return r;
}
__device__ __forceinline__ uint2 splitf(float v) {
    uint32_t h = f2tf32(v);
    return make_uint2(h, f2tf32(v - __uint_as_float(h)));
}

// ---------------- scratch (static __device__, no allocs) ----------------
__device__ float d_mean [BB*CIN];
__device__ float d_std  [BB*CIN];
__device__ float d_pe   [NEXT*DM];             // positional embeds
__device__ float d_scale[BB*NEXT*CIN];
__device__ float d_xz   [NTOK*2048];           // in_proj output (per group: xc|z)
__device__ float d_dbl  [GG*NTOK*40];          // x_proj output (dt_raw|B|C)
// packed (tf32 hi, lo) operand arrays
__device__ uint2 d_Wep  [DM*KE];               // fused embed weight [512][112]
__device__ uint2 d_hwp  [CIN*DM];              // hetero_w [32][512]
__device__ uint2 d_ipwp [GG*512*DG];           // in_proj  [g][512][128]
__device__ uint2 d_xpwp [GG*40*DIN];           // x_proj   [g][40][256]
__device__ uint2 d_opwp [GG*DG*DIN];           // out_proj [g][128][256]
__device__ uint2 d_owp  [CIN*DM];              // out_w    [32][512]
__device__ uint2 d_A1p  [BB*NEXT*KE];
__device__ uint2 d_A2p  [NTOK*KE];
__device__ uint2 d_e1p  [BB*NEXT*DM];
__device__ uint2 d_xcp  [NTOK*DM];
__device__ uint2 d_xconvp[GG*NTOK*DIN];
__device__ uint2 d_yp   [GG*NTOK*DIN];
__device__ uint2 d_xmp  [NTOK*DM];

// ---------------- 1: per-(b,c) mean/std over L ----------------
__global__ void stats_kernel(const float* __restrict__ x_enc) {
    int bc = blockIdx.x;                       // b*32 + c
    const float* xp = x_enc + (size_t)(bc >> 5) * (LL*CIN) + (bc & 31);
    float s = 0.f, sq = 0.f;
    for (int l = threadIdx.x; l < LL; l += 256) {
        float v = xp[(size_t)l * CIN];
        s += v; sq += v * v;
    }
    __shared__ float sh[512];
    sh[threadIdx.x] = s; sh[256 + threadIdx.x] = sq;
    __syncthreads();
    for (int st = 128; st; st >>= 1) {
        if (threadIdx.x < st) {
            sh[threadIdx.x]       += sh[threadIdx.x + st];
            sh[256 + threadIdx.x] += sh[256 + threadIdx.x + st];
        }
        __syncthreads();
    }
    if (threadIdx.x == 0) {
        float m   = sh[0]   * (1.f / LL);
        float var = sh[256] * (1.f / LL) - m * m;
        d_mean[bc] = m;
        d_std[bc]  = sqrtf(var + 1e-5f);
    }
}

// ---------------- 2: split all weights into packed form + pe table -----------
#define S0 (DM*KE)                 // We packed
#define S1 (S0 + NEXT*DM)          // pe float
#define S2 (S1 + CIN*DM)           // hetero
#define S3 (S2 + GG*512*DG)        // in_proj
#define S4 (S3 + GG*40*DIN)        // x_proj
#define S5 (S4 + GG*DG*DIN)        // out_proj
#define S6 (S5 + CIN*DM)           // out_w
__global__ void prep_kernel(const float* __restrict__ conv_w,
                            const float* __restrict__ temp_w,
                            const float* __restrict__ hw,
                            const float* __restrict__ ipw,
                            const float* __restrict__ xpw,
                            const float* __restrict__ opw,
                            const float* __restrict__ ow) {
    int idx = blockIdx.x * blockDim.x + threadIdx.x;
    if (idx < S0) {
        int d = idx / KE, r = idx % KE;
        float v = 0.f;
        if (r < 96)       v = conv_w[d * 96 + (r & 31) * 3 + (r >> 5)];
        else if (r < 100) v = temp_w[d * 4 + (r - 96)];
        d_Wep[idx] = splitf(v);
    } else if (idx < S1) {
        int j = idx - S0;
        int u = j / DM, d = j % DM;
        int l = (u == 0) ? 0 : (926 + u);
        float freq = expf(-(float)(d & ~1) * (LN1E4 / (float)DM));
        float arg  = (float)l * freq;
        d_pe[j] = (d & 1) ? cosf(arg) : sinf(arg);
    } else if (idx < S2) {
        int j = idx - S1; d_hwp[j]  = splitf(hw[j]);
    } else if (idx < S3) {
        int j = idx - S2; d_ipwp[j] = splitf(ipw[j]);
    } else if (idx < S4) {
        int j = idx - S3; d_xpwp[j] = splitf(xpw[j]);
    } else if (idx < S5) {
        int j = idx - S4; d_opwp[j] = splitf(opw[j]);
    } else if (idx < S6) {
        int j = idx - S5; d_owp[j]  = splitf(ow[j]);
    }
}

// ---------------- 3a: build A1 rows (normalized window + mark), packed --------
__global__ void inv1_kernel(const float* __restrict__ x_enc,
                            const float* __restrict__ mark) {
    int row = blockIdx.x;                      // b*NEXT + u
    int tid = threadIdx.x;
    if (tid >= KE) return;
    int u = row % NEXT, b = row / NEXT;
    int l  = (u == 0) ? 0 : (926 + u);
    int lp = (l == 0) ? (LL - 1) : (l - 1);
    int ln = (l == LL - 1) ? 0 : (l + 1);
    float v = 0.f;
    if (tid < 96) {
        int k = tid >> 5, c = tid & 31;
        int ll = (k == 0) ? lp : ((k == 1) ? l : ln);
        float x = x_enc[((size_t)b * LL + ll) * CIN + c];
        v = (x - d_mean[b * CIN + c]) / d_std[b * CIN + c];
    } else if (tid < 100) {
        v = mark[((size_t)b * LL + l) * NMARK + (tid - 96)];
    }
    d_A1p[(size_t)row * KE + tid] = splitf(v);
}

// ---------------- 3b: build A2 rows (normalized*(1+scale) + 2*mark), packed ---
__global__ void inv2_kernel(const float* __restrict__ x_enc,
                            const float* __restrict__ mark) {
    int row = blockIdx.x;                      // tok = b*96 + j
    int tid = threadIdx.x;
    if (tid >= KE) return;
    int b = row / PRED, j = row % PRED;
    int l  = 928 + j;
    int lp = l - 1;
    int ln = (l == LL - 1) ? 0 : (l + 1);
    float v = 0.f;
    if (tid < 96) {
        int k = tid >> 5, c = tid & 31;
        int ll = (k == 0) ? lp : ((k == 1) ? l : ln);
        int u  = (ll == 0) ? 0 : (ll - 926);
        float x  = x_enc[((size_t)b * LL + ll) * CIN + c];
        float xn = (x - d_mean[b * CIN + c]) / d_std[b * CIN + c];
        v = xn * (1.0f + d_scale[((size_t)b * NEXT + u) * CIN + c]);
    } else if (tid < 100) {
        v = 2.0f * mark[((size_t)b * LL + l) * NMARK + (tid - 96)];
    }
    d_A2p[(size_t)row * KE + tid] = splitf(v);
}

// =====================================================================
// TF32 split-3 tensor-core GEMM on PRE-SPLIT operands.
// A,W: packed uint2 (tf32 hi, lo) per element, row-major [rows][K].
// C[M,N] = A @ W^T. 64x64 tile, 128 threads (4 warps, 32x32), BK=8,
// double-buffered. NO conversion in this kernel. Accuracy ~fp32.
// Requires: M%64==0, K%8==0, N even.
// EPI: 0=float out   1=+pe[m%NEXT], packed out   2=+2*pe[m%96+2], packed out
//      3=exp(acc+aux[n]), float     4=denorm, float     5=packed out
// =====================================================================
__device__ __forceinline__ void mma_tf32(float* d, const uint32_t* a, const uint32_t* b) {
    asm volatile("mma.sync.aligned.m16n8k8.row.col.f32.tf32.tf32.f32 "
        "{%0,%1,%2,%3},{%4,%5,%6,%7},{%8,%9},{%0,%1,%2,%3};"
        : "+f"(d[0]), "+f"(d[1]), "+f"(d[2]), "+f"(d[3])
        : "r"(a[0]), "r"(a[1]), "r"(a[2]), "r"(a[3]), "r"(b[0]), "r"(b[1]));
}

template<int EPI>
__global__ void __launch_bounds__(128)
gemm_mma(const uint2* __restrict__ A, const uint2* __restrict__ W,
         void* __restrict__ Cv, const float* __restrict__ aux,
         int M, int N, int K, int lda, int ldw, int ldc,
         long sA, long sW, long sC) {
    int g = blockIdx.z;
    A += (long)g * sA; W += (long)g * sW;
    float* Cf = (float*)Cv + (long)g * sC;
    uint2* Cp = (uint2*)Cv + (long)g * sC;

    __shared__ __align__(16) uint2 As[2][64][12];   // stride 12 uint2: conflict-free
    __shared__ __align__(16) uint2 Ws[2][64][12];

    const int tid = threadIdx.x;
    const int m0 = blockIdx.y * 64, n0 = blockIdx.x * 64;
    const int row = tid >> 1, h4 = (tid & 1) * 4;   // 4 uint2 (=2 uint4) per thread
    const bool wok = (n0 + row) < N;
    const uint2* Ag = A + (size_t)(m0 + row) * lda + h4;
    const uint2* Wg = W + (size_t)(wok ? (n0 + row) : 0) * ldw + h4;
    const uint4 z4 = make_uint4(0u, 0u, 0u, 0u);

    // preload k-tile 0
    {
        uint4 a0 = *(const uint4*)(Ag);
        uint4 a1 = *(const uint4*)(Ag + 2);
        uint4 w0 = wok ? *(const uint4*)(Wg)     : z4;
        uint4 w1 = wok ? *(const uint4*)(Wg + 2) : z4;
        *(uint4*)&As[0][row][h4]     = a0; *(uint4*)&As[0][row][h4 + 2] = a1;
        *(uint4*)&Ws[0][row][h4]     = w0; *(uint4*)&Ws[0][row][h4 + 2] = w1;
    }
    __syncthreads();

    const int lane = tid & 31, grp = lane >> 2, tig = lane & 3;
    const int wid = tid >> 5;
    const int mbase = (wid >> 1) * 32, nbase = (wid & 1) * 32;

    float acc[2][4][4] = {};
    int buf = 0;
    uint4 pa0, pa1, pw0, pw1;

    for (int k0 = 0; k0 < K; k0 += 8) {
        const bool more = (k0 + 8) < K;
        if (more) {
            pa0 = *(const uint4*)(Ag + k0 + 8);
            pa1 = *(const uint4*)(Ag + k0 + 10);
            pw0 = wok ? *(const uint4*)(Wg + k0 + 8)  : z4;
            pw1 = wok ? *(const uint4*)(Wg + k0 + 10) : z4;
        }
        {
            uint32_t Ahi[2][4], Alo[2][4], Bhi[4][2], Blo[4][2];
            #pragma unroll
            for (int mt = 0; mt < 2; mt++) {
                int mr = mbase + mt * 16 + grp;
                uint2 p0 = As[buf][mr][tig];
                uint2 p1 = As[buf][mr + 8][tig];
                uint2 p2 = As[buf][mr][tig + 4];
                uint2 p3 = As[buf][mr + 8][tig + 4];
                Ahi[mt][0] = p0.x; Alo[mt][0] = p0.y;
                Ahi[mt][1] = p1.x; Alo[mt][1] = p1.y;
                Ahi[mt][2] = p2.x; Alo[mt][2] = p2.y;
                Ahi[mt][3] = p3.x; Alo[mt][3] = p3.y;
            }
            #pragma unroll
            for (int nt = 0; nt < 4; nt++) {
                int nc = nbase + nt * 8 + grp;
                uint2 q0 = Ws[buf][nc][tig];
                uint2 q1 = Ws[buf][nc][tig + 4];
                Bhi[nt][0] = q0.x; Blo[nt][0] = q0.y;
                Bhi[nt][1] = q1.x; Blo[nt][1] = q1.y;
            }
            #pragma unroll
            for (int mt = 0; mt < 2; mt++)
                #pragma unroll
                for (int nt = 0; nt < 4; nt++) {
                    mma_tf32(acc[mt][nt], Ahi[mt], Bhi[nt]);
                    mma_tf32(acc[mt][nt], Ahi[mt], Blo[nt]);
                    mma_tf32(acc[mt][nt], Alo[mt], Bhi[nt]);
                }
        }
        if (more) {
            buf ^= 1;
            *(uint4*)&As[buf][row][h4]     = pa0; *(uint4*)&As[buf][row][h4 + 2] = pa1;
            *(uint4*)&Ws[buf][row][h4]     = pw0; *(uint4*)&Ws[buf][row][h4 + 2] = pw1;
            __syncthreads();
        }
    }

    // epilogue: acc[.][nt][c]: c0,c1 -> row grp, cols tig*2,+1; c2,c3 -> row grp+8
    #pragma unroll
    for (int mt = 0; mt < 2; mt++) {
        #pragma unroll
        for (int half = 0; half < 2; half++) {
            int m = m0 + mbase + mt * 16 + grp + half * 8;
            if (m >= M) continue;
            const float* per = nullptr;
            if (EPI == 1) per = d_pe + (size_t)(m % NEXT) * DM;
            if (EPI == 2) per = d_pe + (size_t)(m % PRED + 2) * DM;
            #pragma unroll
            for (int nt = 0; nt < 4; nt++) {
                int n = n0 + nbase + nt * 8 + tig * 2;
                if (n >= N) continue;          // N even, pair handled together
                float v0 = acc[mt][nt][half * 2 + 0];
                float v1 = acc[mt][nt][half * 2 + 1];
                if (EPI == 1) { v0 += per[n];       v1 += per[n + 1]; }
                if (EPI == 2) { v0 += 2.f * per[n]; v1 += 2.f * per[n + 1]; }
                if (EPI == 3) { v0 = expf(v0 + aux[n]); v1 = expf(v1 + aux[n + 1]); }
                if (EPI == 4) {
                    int b = m / PRED;
                    v0 = v0 * d_std[b * CIN + n]     + d_mean[b * CIN + n];
                    v1 = v1 * d_std[b * CIN + n + 1] + d_mean[b * CIN + n + 1];
                }
                if (EPI == 1 || EPI == 2 || EPI == 5) {
                    uint2 s0 = splitf(v0), s1 = splitf(v1);
                    *(uint4*)&Cp[(size_t)m * ldc + n] = make_uint4(s0.x, s0.y, s1.x, s1.y);
                } else {
                    *(float2*)&Cf[(size_t)m * ldc + n] = make_float2(v0, v1);
                }
            }
        }
    }
}

// ---------------- 5: depthwise conv + SiLU, packed output ---------------------
__global__ void __launch_bounds__(256)
conv_silu_kernel(const float* __restrict__ cw, const float* __restrict__ cb) {
    int gid = blockIdx.x;
    int g   = gid / (BB * 6);
    int row = gid % (BB * 6);
    int tok0 = (row / 6) * PRED + (row % 6) * PATCH;
    int e = threadIdx.x;
    float w0 = cw[(g * DIN + e) * 4 + 0];
    float w1 = cw[(g * DIN + e) * 4 + 1];
    float w2 = cw[(g * DIN + e) * 4 + 2];
    float w3 = cw[(g * DIN + e) * 4 + 3];
    float bv = cb[g * DIN + e];
    float h0 = 0.f, h1 = 0.f, h2 = 0.f;
    const float* src = d_xz + (size_t)tok0 * 2048 + g * 512 + e;
    uint2* dst = d_xconvp + (size_t)g * NTOK * DIN + (size_t)tok0 * DIN + e;
    #pragma unroll
    for (int t = 0; t < PATCH; t++) {
        float xv = src[(size_t)t * 2048];
        float acc = bv + w0 * h0 + w1 * h1 + w2 * h2 + w3 * xv;
        h0 = h1; h1 = h2; h2 = xv;
        float sig = 1.0f / (1.0f + expf(-acc));
        dst[(size_t)t * DIN] = splitf(acc * sig);
    }
}

// ---------------- 7: selective scan with fused dt; packed in/out --------------
__global__ void __launch_bounds__(256)
scan_kernel(const float* __restrict__ A_log, const float* __restrict__ Dp,
            const float* __restrict__ dtw, const float* __restrict__ dtb) {
    int gid = blockIdx.x;
    int g   = gid / (BB * 6);
    int row = gid % (BB * 6);
    int tok0 = (row / 6) * PRED + (row % 6) * PATCH;
    int e = threadIdx.x;

    float Av[NST];
    #pragma unroll
    for (int n = 0; n < NST; n++) Av[n] = -expf(A_log[((size_t)g * DIN + e) * NST + n]);
    float Dv = Dp[g * DIN + e];
    float dtbv = dtb[g * DIN + e];
    float4 dw0 = *(const float4*)(dtw + (size_t)(g * DIN + e) * DTR);
    float4 dw1 = *(const float4*)(dtw + (size_t)(g * DIN + e) * DTR + 4);
    float h[NST];
    #pragma unroll
    for (int n = 0; n < NST; n++) h[n] = 0.f;

    __shared__ float sh[40];
    for (int t = 0; t < PATCH; t++) {
        int tok = tok0 + t;
        if (e < 40) sh[e] = d_dbl[((size_t)g * NTOK + tok) * 40 + e];
        __syncthreads();

        float dtv = dtbv
            + sh[0]*dw0.x + sh[1]*dw0.y + sh[2]*dw0.z + sh[3]*dw0.w
            + sh[4]*dw1.x + sh[5]*dw1.y + sh[6]*dw1.z + sh[7]*dw1.w;
        dtv = (dtv > 20.f) ? dtv : log1pf(expf(dtv));

        size_t cidx = (size_t)g * NTOK * DIN + (size_t)tok * DIN + e;
        uint2 xp = d_xconvp[cidx];
        float xv = __uint_as_float(xp.x) + __uint_as_float(xp.y);
        float dx = dtv * xv;
        float y = 0.f;
        #pragma unroll
        for (int n = 0; n < NST; n++) {
            h[n] = __expf(dtv * Av[n]) * h[n] + dx * sh[8 + n];
            y += h[n] * sh[24 + n];
        }
        y += Dv * xv;
        float zv = d_xz[(size_t)tok * 2048 + g * 512 + 256 + e];
        y *= zv / (1.0f + expf(-zv));
        d_yp[cidx] = splitf(y);
        __syncthreads();
    }
}

// ---------------- host launcher ----------------
extern "C" void kernel_launch(void* const* d_in, const int* in_sizes, int n_in,
                              void* d_out, int out_size) {
    const float* x_enc     = (const float*)d_in[0];
    const float* x_mark    = (const float*)d_in[1];
    const float* conv_w    = (const float*)d_in[4];
    const float* temp_w    = (const float*)d_in[5];
    const float* hetero_w  = (const float*)d_in[6];
    const float* hetero_b  = (const float*)d_in[7];
    const float* in_proj_w = (const float*)d_in[8];
    const float* conv1_w   = (const float*)d_in[9];
    const float* conv1_b   = (const float*)d_in[10];
    const float* x_proj_w  = (const float*)d_in[11];
    const float* dt_proj_w = (const float*)d_in[12];
    const float* dt_proj_b = (const float*)d_in[13];
    const float* A_log     = (const float*)d_in[14];
    const float* D_param   = (const float*)d_in[15];
    const float* out_pw    = (const float*)d_in[16];
    const float* out_w     = (const float*)d_in[17];
    float* out = (float*)d_out;

    uint2 *p_A1p, *p_A2p, *p_e1p, *p_xcp, *p_xconvp, *p_yp, *p_xmp;
    uint2 *p_Wep, *p_hwp, *p_ipwp, *p_xpwp, *p_opwp, *p_owp;
    float *p_scale, *p_xz, *p_dbl;
    cudaGetSymbolAddress((void**)&p_A1p,    d_A1p);
    cudaGetSymbolAddress((void**)&p_A2p,    d_A2p);
    cudaGetSymbolAddress((void**)&p_e1p,    d_e1p);
    cudaGetSymbolAddress((void**)&p_xcp,    d_xcp);
    cudaGetSymbolAddress((void**)&p_xconvp, d_xconvp);
    cudaGetSymbolAddress((void**)&p_yp,     d_yp);
    cudaGetSymbolAddress((void**)&p_xmp,    d_xmp);
    cudaGetSymbolAddress((void**)&p_Wep,    d_Wep);
    cudaGetSymbolAddress((void**)&p_hwp,    d_hwp);
    cudaGetSymbolAddress((void**)&p_ipwp,   d_ipwp);
    cudaGetSymbolAddress((void**)&p_xpwp,   d_xpwp);
    cudaGetSymbolAddress((void**)&p_opwp,   d_opwp);
    cudaGetSymbolAddress((void**)&p_owp,    d_owp);
    cudaGetSymbolAddress((void**)&p_scale,  d_scale);
    cudaGetSymbolAddress((void**)&p_xz,     d_xz);
    cudaGetSymbolAddress((void**)&p_dbl,    d_dbl);

    stats_kernel<<<BB * CIN, 256>>>(x_enc);
    prep_kernel<<<(S6 + 255) / 256, 256>>>(conv_w, temp_w, hetero_w,
                                           in_proj_w, x_proj_w, out_pw, out_w);
    inv1_kernel<<<BB * NEXT, 128>>>(x_enc, x_mark);
    // e1 = A1 @ We^T (+pe, packed out): M=3136, N=512, K=112
    gemm_mma<1><<<dim3(8, 49), 128>>>(p_A1p, p_Wep, p_e1p, nullptr,
                                      BB*NEXT, DM, KE, KE, KE, DM, 0, 0, 0);
    // scale = exp(e1 @ hetero_w^T + hb): M=3136, N=32, K=512
    gemm_mma<3><<<dim3(1, 49), 128>>>(p_e1p, p_hwp, p_scale, hetero_b,
                                      BB*NEXT, CIN, DM, DM, DM, CIN, 0, 0, 0);
    inv2_kernel<<<NTOK, 128>>>(x_enc, x_mark);
    // xc = A2 @ We^T (+2*pe, packed out): M=3072, N=512, K=112
    gemm_mma<2><<<dim3(8, 48), 128>>>(p_A2p, p_Wep, p_xcp, nullptr,
                                      NTOK, DM, KE, KE, KE, DM, 0, 0, 0);
    // in_proj batched: (3072 x 512) = (3072 x 128) @ (512 x 128)^T, float out
    gemm_mma<0><<<dim3(8, 48, GG), 128>>>(p_xcp, p_ipwp, p_xz, nullptr,
                                          NTOK, 512, DG, DM, DG, 2048,
                                          DG, (long)512 * DG, 512);
    conv_silu_kernel<<<GG * BB * 6, 256>>>(conv1_w, conv1_b);
    // x_proj batched: (3072 x 40) = (3072 x 256) @ (40 x 256)^T, float out
    gemm_mma<0><<<dim3(1, 48, GG), 128>>>(p_xconvp, p_xpwp, p_dbl, nullptr,
                                          NTOK, 40, DIN, DIN, DIN, 40,
                                          (long)NTOK * DIN, 40L * DIN, (long)NTOK * 40);
    scan_kernel<<<GG * BB * 6, 256>>>(A_log, D_param, dt_proj_w, dt_proj_b);
    // out_proj batched: (3072 x 128) = (3072 x 256) @ (128 x 256)^T, packed out
    gemm_mma<5><<<dim3(2, 48, GG), 128>>>(p_yp, p_opwp, p_xmp, nullptr,
                                          NTOK, DG, DIN, DIN, DIN, DM,
                                          (long)NTOK * DIN, (long)DG * DIN, DG);
    // final: out = (xm @ out_w^T) * std + mean : M=3072, N=32, K=512
    gemm_mma<4><<<dim3(1, 48), 128>>>(p_xmp, p_owp, out, nullptr,
                                      NTOK, CIN, DM, DM, DM, CIN, 0, 0, 0);
}

// round 7
// speedup vs baseline: 1.4885x; 1.4885x over previous
#include <cuda_runtime.h>
#include <cuda_bf16.h>
#include <math.h>
#include <stdint.h>

// ---------------- problem constants ----------------
#define BB    32
#define LL    1024
#define CIN   32
#define DM    512
#define NMARK 4
#define GG    4
#define DG    128
#define DIN   256
#define NST   16
#define DTR   8
#define PATCH 16
#define PRED  96
#define NTOK  (BB*PRED)      // 3072 tokens actually needed
#define NEXT  98             // extended token set: l=0 and l=927..1023
#define KE    112            // embed K padded to multiple of 16
#define LN1E4 9.210340371976184f

// ---------------- bf16 hi/lo pack helpers ----------------
// Packed row layout ("planes per 16-elem tile"): for elements [16t..16t+15],
// words [16t..16t+7] hold bf16x2 HI pairs, words [16t+8..16t+15] hold LO pairs.
// One uint32 word = (elem 2j low half, elem 2j+1 high half). Row = K words total
// (same bytes as fp32).
__device__ __forceinline__ void store_pair(uint32_t* rowbase, int n /*even*/,
                                           float v0, float v1) {
    int w = (n & ~15) + ((n & 15) >> 1);
    uint32_t hw, lw;
    asm("cvt.rn.bf16x2.f32 %0, %1, %2;" : "=r"(hw) : "f"(v1), "f"(v0));
    float h0 = __uint_as_float(hw << 16);
    float h1 = __uint_as_float(hw & 0xffff0000u);
    asm("cvt.rn.bf16x2.f32 %0, %1, %2;" : "=r"(lw) : "f"(v1 - h1), "f"(v0 - h0));
    rowbase[w] = hw;
    rowbase[w + 8] = lw;
}
__device__ __forceinline__ float bf_lo(uint32_t w) { return __uint_as_float(w << 16); }
__device__ __forceinline__ float bf_hi(uint32_t w) { return __uint_as_float(w & 0xffff0000u); }

__device__ __forceinline__ void mma_bf16(float* d, const uint32_t* a, const uint32_t* b) {
    asm volatile("mma.sync.aligned.m16n8k16.row.col.f32.bf16.bf16.f32 "
        "{%0,%1,%2,%3},{%4,%5,%6,%7},{%8,%9},{%0,%1,%2,%3};"
        : "+f"(d[0]), "+f"(d[1]), "+f"(d[2]), "+f"(d[3])
        : "r"(a[0]), "r"(a[1]), "r"(a[2]), "r"(a[3]), "r"(b[0]), "r"(b[1]));
}

// ---------------- scratch (static __device__, no allocs) ----------------
__device__ float d_mean [BB*CIN];
__device__ float d_std  [BB*CIN];
__device__ float d_pe   [NEXT*DM];
__device__ float d_scale[BB*NEXT*CIN];
__device__ float d_xz   [NTOK*2048];           // in_proj output (per group: xc|z), float
__device__ float d_dbl  [GG*NTOK*40];          // x_proj output, float
// packed bf16 hi/lo operand arrays (uint32 words; row length = elem count)
__device__ uint32_t d_Wep  [DM*KE];
__device__ uint32_t d_hwp  [CIN*DM];
__device__ uint32_t d_ipwp [GG*512*DG];
__device__ uint32_t d_xpwp [GG*40*DIN];
__device__ uint32_t d_opwp [GG*DG*DIN];
__device__ uint32_t d_owp  [CIN*DM];
__device__ uint32_t d_A1p  [BB*NEXT*KE];
__device__ uint32_t d_A2p  [NTOK*KE];
__device__ uint32_t d_e1p  [BB*NEXT*DM];
__device__ uint32_t d_xcp  [NTOK*DM];
__device__ uint32_t d_xconvp[GG*NTOK*DIN];
__device__ uint32_t d_yp   [GG*NTOK*DIN];
__device__ uint32_t d_xmp  [NTOK*DM];

// ---------------- 1: per-(b,c) mean/std over L ----------------
__global__ void stats_kernel(const float* __restrict__ x_enc) {
    int bc = blockIdx.x;
    const float* xp = x_enc + (size_t)(bc >> 5) * (LL*CIN) + (bc & 31);
    float s = 0.f, sq = 0.f;
    for (int l = threadIdx.x; l < LL; l += 256) {
        float v = xp[(size_t)l * CIN];
        s += v; sq += v * v;
    }
    __shared__ float sh[512];
    sh[threadIdx.x] = s; sh[256 + threadIdx.x] = sq;
    __syncthreads();
    for (int st = 128; st; st >>= 1) {
        if (threadIdx.x < st) {
            sh[threadIdx.x]       += sh[threadIdx.x + st];
            sh[256 + threadIdx.x] += sh[256 + threadIdx.x + st];
        }
        __syncthreads();
    }
    if (threadIdx.x == 0) {
        float m   = sh[0]   * (1.f / LL);
        float var = sh[256] * (1.f / LL) - m * m;
        d_mean[bc] = m;
        d_std[bc]  = sqrtf(var + 1e-5f);
    }
}

// ---------------- 2: pack all weights + pe table (thread per elem-PAIR) ------
#define P0 (DM*(KE/2))                 // We
#define P1 (P0 + NEXT*DM)              // pe (per float)
#define P2 (P1 + (CIN*DM)/2)           // hetero
#define P3 (P2 + (GG*512*DG)/2)        // in_proj
#define P4 (P3 + (GG*40*DIN)/2)        // x_proj
#define P5 (P4 + (GG*DG*DIN)/2)        // out_proj
#define P6 (P5 + (CIN*DM)/2)           // out_w
__global__ void prep_kernel(const float* __restrict__ conv_w,
                            const float* __restrict__ temp_w,
                            const float* __restrict__ hw,
                            const float* __restrict__ ipw,
                            const float* __restrict__ xpw,
                            const float* __restrict__ opw,
                            const float* __restrict__ ow) {
    int idx = blockIdx.x * blockDim.x + threadIdx.x;
    if (idx < P0) {
        int r = idx / (KE/2), q = idx % (KE/2);
        float v[2];
        #pragma unroll
        for (int i = 0; i < 2; i++) {
            int e = 2*q + i;
            float t = 0.f;
            if (e < 96)       t = conv_w[r * 96 + (e & 31) * 3 + (e >> 5)];
            else if (e < 100) t = temp_w[r * 4 + (e - 96)];
            v[i] = t;
        }
        store_pair(d_Wep + (size_t)r * KE, 2*q, v[0], v[1]);
    } else if (idx < P1) {
        int j = idx - P0;
        int u = j / DM, d = j % DM;
        int l = (u == 0) ? 0 : (926 + u);
        float freq = expf(-(float)(d & ~1) * (LN1E4 / (float)DM));
        float arg  = (float)l * freq;
        d_pe[j] = (d & 1) ? cosf(arg) : sinf(arg);
    } else if (idx < P2) {
        int p = idx - P1; int r = p / (DM/2), q = p % (DM/2);
        store_pair(d_hwp + (size_t)r * DM, 2*q, hw[r*DM + 2*q], hw[r*DM + 2*q + 1]);
    } else if (idx < P3) {
        int p = idx - P2; int r = p / (DG/2), q = p % (DG/2);
        store_pair(d_ipwp + (size_t)r * DG, 2*q, ipw[(size_t)r*DG + 2*q], ipw[(size_t)r*DG + 2*q + 1]);
    } else if (idx < P4) {
        int p = idx - P3; int r = p / (DIN/2), q = p % (DIN/2);
        store_pair(d_xpwp + (size_t)r * DIN, 2*q, xpw[(size_t)r*DIN + 2*q], xpw[(size_t)r*DIN + 2*q + 1]);
    } else if (idx < P5) {
        int p = idx - P4; int r = p / (DIN/2), q = p % (DIN/2);
        store_pair(d_opwp + (size_t)r * DIN, 2*q, opw[(size_t)r*DIN + 2*q], opw[(size_t)r*DIN + 2*q + 1]);
    } else if (idx < P6) {
        int p = idx - P5; int r = p / (DM/2), q = p % (DM/2);
        store_pair(d_owp + (size_t)r * DM, 2*q, ow[(size_t)r*DM + 2*q], ow[(size_t)r*DM + 2*q + 1]);
    }
}

// ---------------- embed-input element value (shared by inv1/inv2) -------------
__device__ __forceinline__ float a1_elem(const float* x_enc, const float* mark,
                                         int b, int l, int lp, int ln, int e) {
    if (e < 96) {
        int k = e >> 5, c = e & 31;
        int ll = (k == 0) ? lp : ((k == 1) ? l : ln);
        float x = x_enc[((size_t)b * LL + ll) * CIN + c];
        return (x - d_mean[b * CIN + c]) / d_std[b * CIN + c];
    } else if (e < 100) {
        return mark[((size_t)b * LL + l) * NMARK + (e - 96)];
    }
    return 0.f;
}

// ---------------- 3a: build packed A1 rows ------------------------------------
__global__ void inv1_kernel(const float* __restrict__ x_enc,
                            const float* __restrict__ mark) {
    int row = blockIdx.x;                      // b*NEXT + u
    int p = threadIdx.x;
    if (p >= KE/2) return;
    int u = row % NEXT, b = row / NEXT;
    int l  = (u == 0) ? 0 : (926 + u);
    int lp = (l == 0) ? (LL - 1) : (l - 1);
    int ln = (l == LL - 1) ? 0 : (l + 1);
    float v0 = a1_elem(x_enc, mark, b, l, lp, ln, 2*p);
    float v1 = a1_elem(x_enc, mark, b, l, lp, ln, 2*p + 1);
    store_pair(d_A1p + (size_t)row * KE, 2*p, v0, v1);
}

// ---------------- 3b: build packed A2 rows ------------------------------------
__device__ __forceinline__ float a2_elem(const float* x_enc, const float* mark,
                                         int b, int l, int lp, int ln, int e) {
    if (e < 96) {
        int k = e >> 5, c = e & 31;
        int ll = (k == 0) ? lp : ((k == 1) ? l : ln);
        int u  = (ll == 0) ? 0 : (ll - 926);
        float x  = x_enc[((size_t)b * LL + ll) * CIN + c];
        float xn = (x - d_mean[b * CIN + c]) / d_std[b * CIN + c];
        return xn * (1.0f + d_scale[((size_t)b * NEXT + u) * CIN + c]);
    } else if (e < 100) {
        return 2.0f * mark[((size_t)b * LL + l) * NMARK + (e - 96)];
    }
    return 0.f;
}
__global__ void inv2_kernel(const float* __restrict__ x_enc,
                            const float* __restrict__ mark) {
    int row = blockIdx.x;                      // tok = b*96 + j
    int p = threadIdx.x;
    if (p >= KE/2) return;
    int b = row / PRED, j = row % PRED;
    int l  = 928 + j;
    int lp = l - 1;
    int ln = (l == LL - 1) ? 0 : (l + 1);
    float v0 = a2_elem(x_enc, mark, b, l, lp, ln, 2*p);
    float v1 = a2_elem(x_enc, mark, b, l, lp, ln, 2*p + 1);
    store_pair(d_A2p + (size_t)row * KE, 2*p, v0, v1);
}

// =====================================================================
// bf16 split-3 tensor-core GEMM on packed operands. C[M,N] = A @ W^T.
// 64x64 tile, 128 threads (4 warps, 32x32 each), BK=16, double-buffered.
// Smem: 4 planes [64][12] uint32, XOR-4 row swizzle -> conflict-free
// loads AND stores. Inner loop: 24 MMA.m16n8k16 + 32 LDS.32, no cvt.
// Requires: M%64==0, K%16==0, N even, lda/ldw word-strides % 16 == 0.
// EPI: 0=float out  1=+pe[m%NEXT] packed  2=+2*pe[m%96+2] packed
//      3=exp(+aux[n]) float  4=denorm float  5=packed
// =====================================================================
template<int EPI>
__global__ void __launch_bounds__(128)
gemm_bf(const uint32_t* __restrict__ A, const uint32_t* __restrict__ W,
        void* __restrict__ Cv, const float* __restrict__ aux,
        int M, int N, int K, int lda, int ldw, int ldc,
        long sA, long sW, long sC) {
    int g = blockIdx.z;
    A += (long)g * sA; W += (long)g * sW;
    float*    Cf = (float*)Cv    + (long)g * sC;
    uint32_t* Cp = (uint32_t*)Cv + (long)g * sC;

    __shared__ uint32_t Ah[2][64][12], Al[2][64][12];
    __shared__ uint32_t Wh[2][64][12], Wl[2][64][12];

    const int tid = threadIdx.x;
    const int m0 = blockIdx.y * 64, n0 = blockIdx.x * 64;
    const int row = tid >> 1, half = tid & 1;
    const int swz = ((row >> 3) & 1) << 2;
    const bool wok = (n0 + row) < N;
    const uint32_t* Ag = A + (size_t)(m0 + row) * lda + 8 * half;
    const uint32_t* Wg = W + (size_t)(wok ? (n0 + row) : 0) * ldw + 8 * half;
    const uint4 z4 = make_uint4(0u, 0u, 0u, 0u);

    {   // preload k-tile 0
        uint4 a0 = *(const uint4*)(Ag),     a1 = *(const uint4*)(Ag + 4);
        uint4 w0 = wok ? *(const uint4*)(Wg) : z4;
        uint4 w1 = wok ? *(const uint4*)(Wg + 4) : z4;
        uint32_t (*dA)[12] = half ? Al[0] : Ah[0];
        uint32_t (*dW)[12] = half ? Wl[0] : Wh[0];
        *(uint4*)&dA[row][swz]     = a0; *(uint4*)&dA[row][swz ^ 4] = a1;
        *(uint4*)&dW[row][swz]     = w0; *(uint4*)&dW[row][swz ^ 4] = w1;
    }
    __syncthreads();

    const int lane = tid & 31, grp = lane >> 2, tig = lane & 3;
    const int wid = tid >> 5;
    const int mbase = (wid >> 1) * 32, nbase = (wid & 1) * 32;

    float acc[2][4][4] = {};
    int buf = 0;
    uint4 pa0, pa1, pw0, pw1;

    for (int k0 = 0; k0 < K; k0 += 16) {
        const bool more = (k0 + 16) < K;
        if (more) {
            pa0 = *(const uint4*)(Ag + k0 + 16);
            pa1 = *(const uint4*)(Ag + k0 + 20);
            pw0 = wok ? *(const uint4*)(Wg + k0 + 16) : z4;
            pw1 = wok ? *(const uint4*)(Wg + k0 + 20) : z4;
        }
        {
            uint32_t ah[2][4], al[2][4], wh[4][2], wl[4][2];
            // A fragments: rows mr (swz 0) and mr+8 (swz 4) -> word swap on +8 rows
            #pragma unroll
            for (int mt = 0; mt < 2; mt++) {
                int mr = mbase + mt * 16 + grp;
                ah[mt][0] = Ah[buf][mr][tig];         al[mt][0] = Al[buf][mr][tig];
                ah[mt][1] = Ah[buf][mr + 8][tig + 4]; al[mt][1] = Al[buf][mr + 8][tig + 4];
                ah[mt][2] = Ah[buf][mr][tig + 4];     al[mt][2] = Al[buf][mr][tig + 4];
                ah[mt][3] = Ah[buf][mr + 8][tig];     al[mt][3] = Al[buf][mr + 8][tig];
            }
            #pragma unroll
            for (int nt = 0; nt < 4; nt++) {
                int nc = nbase + nt * 8 + grp;
                int s = (nt & 1) << 2;                 // row-block parity of nc
                wh[nt][0] = Wh[buf][nc][tig ^ s];       wl[nt][0] = Wl[buf][nc][tig ^ s];
                wh[nt][1] = Wh[buf][nc][(tig + 4) ^ s]; wl[nt][1] = Wl[buf][nc][(tig + 4) ^ s];
            }
            #pragma unroll
            for (int mt = 0; mt < 2; mt++)
                #pragma unroll
                for (int nt = 0; nt < 4; nt++) {
                    mma_bf16(acc[mt][nt], ah[mt], wh[nt]);
                    mma_bf16(acc[mt][nt], ah[mt], wl[nt]);
                    mma_bf16(acc[mt][nt], al[mt], wh[nt]);
                }
        }
        if (more) {
            buf ^= 1;
            uint32_t (*dA)[12] = half ? Al[buf] : Ah[buf];
            uint32_t (*dW)[12] = half ? Wl[buf] : Wh[buf];
            *(uint4*)&dA[row][swz]     = pa0; *(uint4*)&dA[row][swz ^ 4] = pa1;
            *(uint4*)&dW[row][swz]     = pw0; *(uint4*)&dW[row][swz ^ 4] = pw1;
            __syncthreads();
        }
    }

    // epilogue: c0,c1 -> row grp, cols 2tig,2tig+1; c2,c3 -> row grp+8
    #pragma unroll
    for (int mt = 0; mt < 2; mt++) {
        #pragma unroll
        for (int hh = 0; hh < 2; hh++) {
            int m = m0 + mbase + mt * 16 + grp + hh * 8;
            if (m >= M) continue;
            const float* per = nullptr;
            if (EPI == 1) per = d_pe + (size_t)(m % NEXT) * DM;
            if (EPI == 2) per = d_pe + (size_t)(m % PRED + 2) * DM;
            #pragma unroll
            for (int nt = 0; nt < 4; nt++) {
                int n = n0 + nbase + nt * 8 + tig * 2;
                if (n >= N) continue;
                float v0 = acc[mt][nt][hh * 2 + 0];
                float v1 = acc[mt][nt][hh * 2 + 1];
                if (EPI == 1) { v0 += per[n];       v1 += per[n + 1]; }
                if (EPI == 2) { v0 += 2.f * per[n]; v1 += 2.f * per[n + 1]; }
                if (EPI == 3) { v0 = expf(v0 + aux[n]); v1 = expf(v1 + aux[n + 1]); }
                if (EPI == 4) {
                    int b = m / PRED;
                    v0 = v0 * d_std[b * CIN + n]     + d_mean[b * CIN + n];
                    v1 = v1 * d_std[b * CIN + n + 1] + d_mean[b * CIN + n + 1];
                }
                if (EPI == 1 || EPI == 2 || EPI == 5)
                    store_pair(Cp + (size_t)m * ldc, n, v0, v1);
                else
                    *(float2*)&Cf[(size_t)m * ldc + n] = make_float2(v0, v1);
            }
        }
    }
}

// ---------------- 5: depthwise conv + SiLU; 2 channels/thread, packed out -----
__global__ void __launch_bounds__(128)
conv_silu_kernel(const float* __restrict__ cw, const float* __restrict__ cb) {
    int gid = blockIdx.x;
    int g   = gid / (BB * 6);
    int row = gid % (BB * 6);
    int tok0 = (row / 6) * PRED + (row % 6) * PATCH;
    int t2 = threadIdx.x;                      // pair index 0..127
    int e0 = 2 * t2;
    float4 wa = *(const float4*)(cw + (size_t)(g * DIN + e0) * 4);
    float4 wb = *(const float4*)(cw + (size_t)(g * DIN + e0 + 1) * 4);
    float2 bv = *(const float2*)(cb + g * DIN + e0);
    float a0 = 0.f, a1 = 0.f, a2 = 0.f;        // history chan e0
    float b0 = 0.f, b1 = 0.f, b2 = 0.f;        // history chan e0+1
    const float* src = d_xz + (size_t)tok0 * 2048 + g * 512 + e0;
    #pragma unroll
    for (int t = 0; t < PATCH; t++) {
        float2 xv = *(const float2*)(src + (size_t)t * 2048);
        float accA = bv.x + wa.x * a0 + wa.y * a1 + wa.z * a2 + wa.w * xv.x;
        float accB = bv.y + wb.x * b0 + wb.y * b1 + wb.z * b2 + wb.w * xv.y;
        a0 = a1; a1 = a2; a2 = xv.x;
        b0 = b1; b1 = b2; b2 = xv.y;
        float sA = accA / (1.0f + expf(-accA));
        float sB = accB / (1.0f + expf(-accB));
        store_pair(d_xconvp + ((size_t)g * NTOK + tok0 + t) * DIN, e0, sA, sB);
    }
}

// ---------------- 7: selective scan (fused dt); packed in/out -----------------
__global__ void __launch_bounds__(256)
scan_kernel(const float* __restrict__ A_log, const float* __restrict__ Dp,
            const float* __restrict__ dtw, const float* __restrict__ dtb) {
    int gid = blockIdx.x;
    int g   = gid / (BB * 6);
    int row = gid % (BB * 6);
    int tok0 = (row / 6) * PRED + (row % 6) * PATCH;
    int e = threadIdx.x;

    float Av[NST];
    #pragma unroll
    for (int n = 0; n < NST; n++) Av[n] = -expf(A_log[((size_t)g * DIN + e) * NST + n]);
    float Dv = Dp[g * DIN + e];
    float dtbv = dtb[g * DIN + e];
    float4 dw0 = *(const float4*)(dtw + (size_t)(g * DIN + e) * DTR);
    float4 dw1 = *(const float4*)(dtw + (size_t)(g * DIN + e) * DTR + 4);
    float h[NST];
    #pragma unroll
    for (int n = 0; n < NST; n++) h[n] = 0.f;

    const int wi = (e & ~15) + ((e & 15) >> 1);
    const bool odd = e & 1;

    __shared__ float sh[40];
    for (int t = 0; t < PATCH; t++) {
        int tok = tok0 + t;
        if (e < 40) sh[e] = d_dbl[((size_t)g * NTOK + tok) * 40 + e];
        __syncthreads();

        float dtv = dtbv
            + sh[0]*dw0.x + sh[1]*dw0.y + sh[2]*dw0.z + sh[3]*dw0.w
            + sh[4]*dw1.x + sh[5]*dw1.y + sh[6]*dw1.z + sh[7]*dw1.w;
        dtv = (dtv > 20.f) ? dtv : log1pf(expf(dtv));

        size_t rb = ((size_t)g * NTOK + tok) * DIN;
        uint32_t whi = d_xconvp[rb + wi], wlo = d_xconvp[rb + wi + 8];
        float xv = odd ? (bf_hi(whi) + bf_hi(wlo)) : (bf_lo(whi) + bf_lo(wlo));
        float dx = dtv * xv;
        float y = 0.f;
        #pragma unroll
        for (int n = 0; n < NST; n++) {
            h[n] = __expf(dtv * Av[n]) * h[n] + dx * sh[8 + n];
            y += h[n] * sh[24 + n];
        }
        y += Dv * xv;
        float zv = d_xz[(size_t)tok * 2048 + g * 512 + 256 + e];
        y *= zv / (1.0f + expf(-zv));
        float y1 = __shfl_down_sync(0xffffffffu, y, 1);
        if (!odd) store_pair(d_yp + rb, e, y, y1);
        __syncthreads();
    }
}

// ---------------- host launcher ----------------
extern "C" void kernel_launch(void* const* d_in, const int* in_sizes, int n_in,
                              void* d_out, int out_size) {
    const float* x_enc     = (const float*)d_in[0];
    const float* x_mark    = (const float*)d_in[1];
    const float* conv_w    = (const float*)d_in[4];
    const float* temp_w    = (const float*)d_in[5];
    const float* hetero_w  = (const float*)d_in[6];
    const float* hetero_b  = (const float*)d_in[7];
    const float* in_proj_w = (const float*)d_in[8];
    const float* conv1_w   = (const float*)d_in[9];
    const float* conv1_b   = (const float*)d_in[10];
    const float* x_proj_w  = (const float*)d_in[11];
    const float* dt_proj_w = (const float*)d_in[12];
    const float* dt_proj_b = (const float*)d_in[13];
    const float* A_log     = (const float*)d_in[14];
    const float* D_param   = (const float*)d_in[15];
    const float* out_pw    = (const float*)d_in[16];
    const float* out_w     = (const float*)d_in[17];
    float* out = (float*)d_out;

    uint32_t *p_A1p, *p_A2p, *p_e1p, *p_xcp, *p_xconvp, *p_yp, *p_xmp;
    uint32_t *p_Wep, *p_hwp, *p_ipwp, *p_xpwp, *p_opwp, *p_owp;
    float *p_scale, *p_xz, *p_dbl;
    cudaGetSymbolAddress((void**)&p_A1p,    d_A1p);
    cudaGetSymbolAddress((void**)&p_A2p,    d_A2p);
    cudaGetSymbolAddress((void**)&p_e1p,    d_e1p);
    cudaGetSymbolAddress((void**)&p_xcp,    d_xcp);
    cudaGetSymbolAddress((void**)&p_xconvp, d_xconvp);
    cudaGetSymbolAddress((void**)&p_yp,     d_yp);
    cudaGetSymbolAddress((void**)&p_xmp,    d_xmp);
    cudaGetSymbolAddress((void**)&p_Wep,    d_Wep);
    cudaGetSymbolAddress((void**)&p_hwp,    d_hwp);
    cudaGetSymbolAddress((void**)&p_ipwp,   d_ipwp);
    cudaGetSymbolAddress((void**)&p_xpwp,   d_xpwp);
    cudaGetSymbolAddress((void**)&p_opwp,   d_opwp);
    cudaGetSymbolAddress((void**)&p_owp,    d_owp);
    cudaGetSymbolAddress((void**)&p_scale,  d_scale);
    cudaGetSymbolAddress((void**)&p_xz,     d_xz);
    cudaGetSymbolAddress((void**)&p_dbl,    d_dbl);

    stats_kernel<<<BB * CIN, 256>>>(x_enc);
    prep_kernel<<<(P6 + 255) / 256, 256>>>(conv_w, temp_w, hetero_w,
                                           in_proj_w, x_proj_w, out_pw, out_w);
    inv1_kernel<<<BB * NEXT, 64>>>(x_enc, x_mark);
    // e1 = A1 @ We^T (+pe, packed): M=3136, N=512, K=112
    gemm_bf<1><<<dim3(8, 49), 128>>>(p_A1p, p_Wep, p_e1p, nullptr,
                                     BB*NEXT, DM, KE, KE, KE, DM, 0, 0, 0);
    // scale = exp(e1 @ hetero_w^T + hb): M=3136, N=32, K=512, float out
    gemm_bf<3><<<dim3(1, 49), 128>>>(p_e1p, p_hwp, p_scale, hetero_b,
                                     BB*NEXT, CIN, DM, DM, DM, CIN, 0, 0, 0);
    inv2_kernel<<<NTOK, 64>>>(x_enc, x_mark);
    // xc = A2 @ We^T (+2*pe, packed): M=3072, N=512, K=112
    gemm_bf<2><<<dim3(8, 48), 128>>>(p_A2p, p_Wep, p_xcp, nullptr,
                                     NTOK, DM, KE, KE, KE, DM, 0, 0, 0);
    // in_proj batched: (3072x512) = (3072x128)@(512x128)^T, float out
    gemm_bf<0><<<dim3(8, 48, GG), 128>>>(p_xcp, p_ipwp, p_xz, nullptr,
                                         NTOK, 512, DG, DM, DG, 2048,
                                         DG, (long)512 * DG, 512);
    conv_silu_kernel<<<GG * BB * 6, 128>>>(conv1_w, conv1_b);
    // x_proj batched: (3072x40) = (3072x256)@(40x256)^T, float out
    gemm_bf<0><<<dim3(1, 48, GG), 128>>>(p_xconvp, p_xpwp, p_dbl, nullptr,
                                         NTOK, 40, DIN, DIN, DIN, 40,
                                         (long)NTOK * DIN, 40L * DIN, (long)NTOK * 40);
    scan_kernel<<<GG * BB * 6, 256>>>(A_log, D_param, dt_proj_w, dt_proj_b);
    // out_proj batched: (3072x128) = (3072x256)@(128x256)^T, packed out
    gemm_bf<5><<<dim3(2, 48, GG), 128>>>(p_yp, p_opwp, p_xmp, nullptr,
                                         NTOK, DG, DIN, DIN, DIN, DM,
                                         (long)NTOK * DIN, (long)DG * DIN, DG);
    // final: out = (xm @ out_w^T)*std+mean : M=3072, N=32, K=512, float out
    gemm_bf<4><<<dim3(1, 48), 128>>>(p_xmp, p_owp, out, nullptr,
                                     NTOK, CIN, DM, DM, DM, CIN, 0, 0, 0);
}